// round 14
// baseline (speedup 1.0000x reference)
#include <cuda_runtime.h>
#include <cstdint>

// BATCH=16384, NCONDS=50, EMB=64, table rows=100002
// d_in[0]: int32 input [B,51]   d_in[1]: float table [100002,64]
// out: float [B, 64 + 50*64]

constexpr int EMB     = 64;
constexpr int NCONDS  = 50;
constexpr int ROW_IN  = 1 + NCONDS;           // 51
constexpr int ROW_OUT = EMB + NCONDS * EMB;   // 3264

__global__ __launch_bounds__(256, 7) void cond_filter_kernel(
    const int*   __restrict__ inp,
    const float* __restrict__ table,
    float*       __restrict__ out,
    int batch)
{
    const unsigned FULL = 0xffffffffu;
    const int warp = (blockIdx.x * blockDim.x + threadIdx.x) >> 5;
    const int lane = threadIdx.x & 31;
    if (warp >= batch) return;

    const int half = lane >> 4;     // 0: even conds, 1: odd conds
    const int hl   = lane & 15;     // lane within 16-lane group (float4 slot)

    const int* row  = inp + (long)warp * ROW_IN;
    float*     orow = out + (long)warp * ROW_OUT;

    // ---- event embedding (both halves load; event_nrm needed in all lanes) ----
    const int e = __ldg(row);
    const float4 ev = *reinterpret_cast<const float4*>(table + (long)e * EMB + 4 * hl);

    if (half == 0)  // write un-normalized event embedding (streaming: no reuse)
        __stcs(reinterpret_cast<float4*>(orow + 4 * hl), ev);

    // reduce within the 16-lane half only (each half holds all 64 floats)
    float ss = ev.x * ev.x + ev.y * ev.y + ev.z * ev.z + ev.w * ev.w;
    #pragma unroll
    for (int o = 8; o; o >>= 1) ss += __shfl_xor_sync(FULL, ss, o);
    const float rinv = rsqrtf(ss);
    const float enx = ev.x * rinv, eny = ev.y * rinv;
    const float enz = ev.z * rinv, enw = ev.w * rinv;

    // ---- conditions, 2 per iteration (one per 16-lane half) ----
    // filtered_c = cond * dot(event_nrm, cond) / dot(cond, cond)
    // Distance-2 gather pipeline: two condition-pairs in flight.
    float4 cv0, cv1;
    {
        const int i0 = __ldg(row + 1 + half);
        cv0 = *reinterpret_cast<const float4*>(table + (long)i0 * EMB + 4 * hl);
        const int i1 = __ldg(row + 3 + half);
        cv1 = *reinterpret_cast<const float4*>(table + (long)i1 * EMB + 4 * hl);
    }

    float* ocond = orow + EMB + (long)half * EMB + 4 * hl;

    #pragma unroll 1
    for (int c = 0; c < NCONDS; c += 2) {
        const float4 a = cv0;
        cv0 = cv1;
        if (c + 4 < NCONDS) {  // prefetch pair c+4 (two pairs in flight)
            const int ci = __ldg(row + 5 + c + half);
            cv1 = *reinterpret_cast<const float4*>(table + (long)ci * EMB + 4 * hl);
        }

        float p = enx * a.x + eny * a.y + enz * a.z + enw * a.w;   // dot(e_n, c)
        float q = a.x * a.x + a.y * a.y + a.z * a.z + a.w * a.w;   // dot(c, c)

        // two independent 4-deep butterflies (dual-issue, no packing SELs)
        #pragma unroll
        for (int o = 8; o; o >>= 1) {
            p += __shfl_xor_sync(FULL, p, o);
            q += __shfl_xor_sync(FULL, q, o);
        }

        const float s = __fdividef(p, q);
        float4 w;
        w.x = a.x * s; w.y = a.y * s; w.z = a.z * s; w.w = a.w * s;
        __stcs(reinterpret_cast<float4*>(ocond + (long)c * EMB), w);
    }
}

extern "C" void kernel_launch(void* const* d_in, const int* in_sizes, int n_in,
                              void* d_out, int out_size)
{
    const int*   inp   = (const int*)d_in[0];
    const float* table = (const float*)d_in[1];
    float*       out   = (float*)d_out;

    const int batch = in_sizes[0] / ROW_IN;

    const int threads = 256;                  // 8 warps/block, 1 warp/row
    const int blocks  = (batch + 7) / 8;

    cond_filter_kernel<<<blocks, threads>>>(inp, table, out, batch);
}